// round 12
// baseline (speedup 1.0000x reference)
#include <cuda_runtime.h>
#include <cstdint>

// Depth-to-space k=3 (CRD): out[b, 3i+r, 3j+s] = in[b, 3r+s, i, j]
//   in : (32, 9, 512, 512) fp32   out: (32, 1, 1536, 1536) fp32
//
// R11 -> R12: identical structure (18 coalesced LDG.32/thread -> stride-3
// conflict-free STS scatter -> ONE 18KB cp.async.bulk smem->gmem per block),
// but the tail waits for FULL completion (wait_group 0, writes visible)
// instead of wait_group.read 0. R11 exported its write-drain to the
// inter-replay boundary (ncu 85.4us but bench 92.2us); waiting in-kernel
// lets the 7 co-resident blocks/SM hide the drain instead.
//
// 256 thr, 18KB smem -> 8 blocks/SM. Grid = 32*512 = 16384.

#define THREADS 256
#define ROW3 4608            // 3 * 1536 floats = 18KB
#define ROW3_BYTES 18432

__global__ __launch_bounds__(THREADS) void d2s_k3_tma_w_kernel(
    const float* __restrict__ in, float* __restrict__ out)
{
    __shared__ __align__(128) float rows[ROW3];

    const int tid = threadIdx.x;
    const int bi  = blockIdx.x;        // b*512 + i
    const int i   = bi & 511;
    const int b   = bi >> 9;

    const float* ip = in + (size_t)b * 9 * 262144 + (size_t)i * 512;

    // 18 fully-coalesced independent streaming loads, conflict-free scatter
    #pragma unroll
    for (int l = 0; l < 18; ++l) {
        const int t   = tid + l * THREADS;   // 0..4607
        const int c   = t >> 9;              // channel 0..8 (const per l)
        const int col = t & 511;
        float v = __ldcs(ip + c * 262144 + col);
        const int r = c / 3;
        const int s = c - 3 * r;
        rows[r * 1536 + 3 * col + s] = v;
    }

    __syncthreads();

    if (tid == 0) {
        // make generic-proxy STS visible to the async (TMA) proxy
        asm volatile("fence.proxy.async.shared::cta;" ::: "memory");

        uint32_t saddr;
        asm("{ .reg .u64 t; cvta.to.shared.u64 t, %1; cvt.u32.u64 %0, t; }"
            : "=r"(saddr) : "l"(rows));

        float* dst = out + (size_t)(b * 1536 + 3 * i) * 1536;  // 18KB contig

        asm volatile(
            "cp.async.bulk.global.shared::cta.bulk_group [%0], [%1], %2;"
            :: "l"(dst), "r"(saddr), "r"(ROW3_BYTES) : "memory");
        asm volatile("cp.async.bulk.commit_group;" ::: "memory");
        // FULL completion: writes visible before block retires, so the
        // drain is hidden by co-resident blocks, not the next graph replay.
        asm volatile("cp.async.bulk.wait_group 0;" ::: "memory");
    }
}

extern "C" void kernel_launch(void* const* d_in, const int* in_sizes, int n_in,
                              void* d_out, int out_size)
{
    const float* in  = (const float*)d_in[0];
    float*       out = (float*)d_out;

    d2s_k3_tma_w_kernel<<<32 * 512, THREADS>>>(in, out);
}

// round 13
// speedup vs baseline: 1.0202x; 1.0202x over previous
#include <cuda_runtime.h>

// Depth-to-space k=3 (CRD): out[b, 3i+r, 3j+s] = in[b, 3r+s, i, j]
//   in : (32, 9, 512, 512) fp32   out: (32, 1, 1536, 1536) fp32
//
// CHAMPION (R8 config, confirmed over 5 alternative structures):
// One block per INPUT row (b, i) -> 3 contiguous output rows (18KB).
//
//  - 18 independent, fully-coalesced streaming LDG.32 per thread
//    (deep MLP; front-batched by ptxas)
//  - stride-3 word scatter into smem: gcd(3,32)=1 -> bank-conflict-free
//    (float4 loads would force stride-12 / 4-way conflicts -> rejected)
//  - one barrier per 36KB of traffic
//  - coalesced float4 streaming stores of 18KB contiguous output
//  - 256 thr x 18KB smem -> 8 blocks/SM = full 2048 threads (the unique
//    occupancy-optimal point: 128thr is smem-limited to 75% occ)
//
// Measured ceiling: ~6.4 TB/s mixed R/W (80% of HBM spec) across five
// structural variants (split-phase 512/256, row-pair 4KB bursts, SW
// pipeline, TMA bulk store x2) -- DRAM-turnaround-bound, not SM-bound.

#define THREADS 256
#define ROW3 4608            // 3 * 1536 floats = 18KB

__global__ __launch_bounds__(THREADS) void d2s_k3_row3_b256_kernel(
    const float* __restrict__ in, float* __restrict__ out)
{
    __shared__ float rows[ROW3];

    const int tid = threadIdx.x;
    const int bi  = blockIdx.x;        // b*512 + i
    const int i   = bi & 511;
    const int b   = bi >> 9;

    // base of (batch b, input row i), channel 0
    const float* ip = in + (size_t)b * 9 * 262144 + (size_t)i * 512;

    // 18 fully-coalesced, independent streaming loads per thread
    #pragma unroll
    for (int l = 0; l < 18; ++l) {
        int t   = tid + l * THREADS;   // 0..4607
        int c   = t >> 9;              // channel 0..8 (compile-time per l)
        int col = t & 511;             // input column
        float v = __ldcs(ip + c * 262144 + col);
        int r = c / 3;
        int s = c - 3 * r;
        rows[r * 1536 + 3 * col + s] = v;   // conflict-free stride-3 scatter
    }

    __syncthreads();

    // 18KB contiguous output: rows 3i..3i+2 of batch b, coalesced float4
    const float4* rv = reinterpret_cast<const float4*>(rows);
    float4* op = reinterpret_cast<float4*>(
        out + (size_t)(b * 1536 + 3 * i) * 1536);

    #pragma unroll
    for (int l = 0; l < 4; ++l)
        __stcs(&op[tid + l * THREADS], rv[tid + l * THREADS]);
    if (tid < 128)
        __stcs(&op[tid + 1024], rv[tid + 1024]);
}

extern "C" void kernel_launch(void* const* d_in, const int* in_sizes, int n_in,
                              void* d_out, int out_size)
{
    const float* in  = (const float*)d_in[0];
    float*       out = (float*)d_out;

    d2s_k3_row3_b256_kernel<<<32 * 512, THREADS>>>(in, out);
}